// round 4
// baseline (speedup 1.0000x reference)
#include <cuda_runtime.h>
#include <cuda_bf16.h>
#include <cuda_fp16.h>
#include <cstdint>

// ---------------------------------------------------------------------------
// EarthAttention3D: B_=960, L=144, C=192, H=6, hd=32, NUM_WINDOWS=64, W_WINS=15
// Round 4: tensor-core (mma.sync) attention with fp16 hi/lo split Q/K/V,
// fp16 P; bf16-split GEMMs for projections (unchanged from R3).
// ---------------------------------------------------------------------------

#define NWIN   960
#define LTOK   144
#define CDIM   192
#define HEADS  6
#define HD     32
#define NW     64
#define WWINS  15
#define MTOT   (NWIN * LTOK)          // 138240
#define QK_SCALE 0.17677669529663687f

// ------------------------- scratch (device globals) ------------------------
__device__ float g_bias[NW * HEADS * LTOK * LTOK];
__device__ __half g_Qh[NWIN * HEADS * LTOK * HD];
__device__ __half g_Ql[NWIN * HEADS * LTOK * HD];
__device__ __half g_Kh[NWIN * HEADS * LTOK * HD];
__device__ __half g_Kl[NWIN * HEADS * LTOK * HD];
__device__ __half g_Vh[NWIN * HEADS * LTOK * HD];
__device__ __half g_Vl[NWIN * HEADS * LTOK * HD];
__device__ __nv_bfloat16 g_Xh[MTOT * CDIM];
__device__ __nv_bfloat16 g_Xl[MTOT * CDIM];
__device__ __nv_bfloat16 g_CtxH[MTOT * CDIM];
__device__ __nv_bfloat16 g_CtxL[MTOT * CDIM];
__device__ __nv_bfloat16 g_W1h[576 * 192];
__device__ __nv_bfloat16 g_W1l[576 * 192];
__device__ __nv_bfloat16 g_W2h[192 * 192];
__device__ __nv_bfloat16 g_W2l[192 * 192];

// ------------------------------ helpers ------------------------------------
__device__ __forceinline__ uint32_t smem_u32(const void* p) {
    uint32_t a;
    asm("{ .reg .u64 t; cvta.to.shared.u64 t, %1; cvt.u32.u64 %0, t; }"
        : "=r"(a) : "l"(p));
    return a;
}
__device__ __forceinline__ void bsplit(float v, __nv_bfloat16& h, __nv_bfloat16& l) {
    h = __float2bfloat16(v);
    l = __float2bfloat16(v - __bfloat162float(h));
}
__device__ __forceinline__ void hsplit(float v, __half& h, __half& l) {
    h = __float2half_rn(v);
    l = __float2half_rn(v - __half2float(h));
}

#define LDSM_X4(r0, r1, r2, r3, addr)                                          \
    asm volatile("ldmatrix.sync.aligned.m8n8.x4.shared.b16 {%0,%1,%2,%3}, [%4];" \
                 : "=r"(r0), "=r"(r1), "=r"(r2), "=r"(r3) : "r"(addr))

#define MMA_BF16(d, a, b)                                                      \
    asm volatile("mma.sync.aligned.m16n8k16.row.col.f32.bf16.bf16.f32 "        \
                 "{%0,%1,%2,%3}, {%4,%5,%6,%7}, {%8,%9}, {%0,%1,%2,%3};"       \
                 : "+f"((d)[0]), "+f"((d)[1]), "+f"((d)[2]), "+f"((d)[3])      \
                 : "r"((a)[0]), "r"((a)[1]), "r"((a)[2]), "r"((a)[3]),         \
                   "r"((b)[0]), "r"((b)[1]))

#define MMA_F16(d, a, b)                                                       \
    asm volatile("mma.sync.aligned.m16n8k16.row.col.f32.f16.f16.f32 "          \
                 "{%0,%1,%2,%3}, {%4,%5,%6,%7}, {%8,%9}, {%0,%1,%2,%3};"       \
                 : "+f"((d)[0]), "+f"((d)[1]), "+f"((d)[2]), "+f"((d)[3])      \
                 : "r"((a)[0]), "r"((a)[1]), "r"((a)[2]), "r"((a)[3]),         \
                   "r"((b)[0]), "r"((b)[1]))

// ---------------------------------------------------------------------------
// Prep: fp32 -> bf16 hi/lo splits
// ---------------------------------------------------------------------------
__global__ void splitX_kernel(const float* __restrict__ x,
                              __nv_bfloat16* __restrict__ h,
                              __nv_bfloat16* __restrict__ l, int n4) {
    int i = blockIdx.x * blockDim.x + threadIdx.x;
    if (i >= n4) return;
    float4 v = reinterpret_cast<const float4*>(x)[i];
    __nv_bfloat16 h0, h1, h2, h3, l0, l1, l2, l3;
    bsplit(v.x, h0, l0); bsplit(v.y, h1, l1);
    bsplit(v.z, h2, l2); bsplit(v.w, h3, l3);
    reinterpret_cast<__nv_bfloat162*>(h)[2 * i]     = __halves2bfloat162(h0, h1);
    reinterpret_cast<__nv_bfloat162*>(h)[2 * i + 1] = __halves2bfloat162(h2, h3);
    reinterpret_cast<__nv_bfloat162*>(l)[2 * i]     = __halves2bfloat162(l0, l1);
    reinterpret_cast<__nv_bfloat162*>(l)[2 * i + 1] = __halves2bfloat162(l2, l3);
}

__global__ void splitW_kernel(const float* __restrict__ W,
                              __nv_bfloat16* __restrict__ h,
                              __nv_bfloat16* __restrict__ l, int N) {
    int idx = blockIdx.x * blockDim.x + threadIdx.x;
    if (idx >= N * 192) return;
    int n = idx / 192, k = idx - n * 192;
    __nv_bfloat16 hh, ll;
    bsplit(W[(size_t)k * N + n], hh, ll);
    h[idx] = hh; l[idx] = ll;
}

// ---------------------------------------------------------------------------
// K0: bias gather (split 4x for latency)
// ---------------------------------------------------------------------------
__global__ void bias_gather_kernel(const float* __restrict__ table,
                                   const int* __restrict__ pidx) {
    const int nwh = blockIdx.x >> 2;
    const int part = blockIdx.x & 3;
    const int nw = nwh / HEADS, h = nwh % HEADS;
    float* dst = g_bias + (size_t)nwh * (LTOK * LTOK);
    for (int i = part * 5184 + threadIdx.x; i < (part + 1) * 5184; i += 256) {
        int pi = pidx[i];
        dst[i] = table[((size_t)pi * NW + nw) * HEADS + h];
    }
}

// ---------------------------------------------------------------------------
// Split-bf16 GEMM via mma.sync: C[M, Ntot] = A[M,192] @ Bt[Ntot,192]^T + bias
//   mode 0 -> scatter fp16-split Q(scaled)/K/V head-major; mode 1 -> out.
// ---------------------------------------------------------------------------
#define ASTR 200
#define GEMM_SMEM ((2 * 128 * ASTR + 2 * 64 * ASTR) * 2)  // 153600 B

__global__ __launch_bounds__(256) void mma_gemm_kernel(
    const __nv_bfloat16* __restrict__ Ah, const __nv_bfloat16* __restrict__ Al,
    const __nv_bfloat16* __restrict__ Bh, const __nv_bfloat16* __restrict__ Bl,
    const float* __restrict__ bias, int ntiles, int mode,
    float* __restrict__ out) {
    extern __shared__ __align__(16) __nv_bfloat16 sb[];
    __nv_bfloat16* sAh = sb;
    __nv_bfloat16* sAl = sb + 128 * ASTR;
    __nv_bfloat16* sBh = sb + 2 * 128 * ASTR;
    __nv_bfloat16* sBl = sBh + 64 * ASTR;

    const int tid = threadIdx.x;
    const int warp = tid >> 5, lane = tid & 31;
    const int warpm = warp >> 1, warpn = warp & 1;
    const int m_blk = blockIdx.x * 128;

    for (int i = tid; i < 128 * 24; i += 256) {
        int r = i / 24, c = (i % 24) * 8;
        *reinterpret_cast<uint4*>(&sAh[r * ASTR + c]) =
            *reinterpret_cast<const uint4*>(&Ah[(size_t)(m_blk + r) * 192 + c]);
        *reinterpret_cast<uint4*>(&sAl[r * ASTR + c]) =
            *reinterpret_cast<const uint4*>(&Al[(size_t)(m_blk + r) * 192 + c]);
    }
    __syncthreads();

    const int lr = lane & 7, sel = lane >> 3;
    const int a_row_off = lr + (sel & 1) * 8;
    const int a_col_off = (sel >> 1) * 8;
    const int b_row_off = lr + (sel >> 1) * 8;
    const int b_col_off = (sel & 1) * 8;

    for (int nt = 0; nt < ntiles; nt++) {
        for (int i = tid; i < 64 * 24; i += 256) {
            int r = i / 24, c = (i % 24) * 8;
            *reinterpret_cast<uint4*>(&sBh[r * ASTR + c]) =
                *reinterpret_cast<const uint4*>(&Bh[(size_t)(nt * 64 + r) * 192 + c]);
            *reinterpret_cast<uint4*>(&sBl[r * ASTR + c]) =
                *reinterpret_cast<const uint4*>(&Bl[(size_t)(nt * 64 + r) * 192 + c]);
        }
        __syncthreads();

        float acc[2][4][4];
#pragma unroll
        for (int mt = 0; mt < 2; mt++)
#pragma unroll
            for (int t4 = 0; t4 < 4; t4++)
#pragma unroll
                for (int j = 0; j < 4; j++) acc[mt][t4][j] = 0.f;

#pragma unroll 4
        for (int ks = 0; ks < 12; ks++) {
            const int k0 = ks * 16;
            uint32_t ah[2][4], al[2][4], bh[4][2], bl[4][2];
#pragma unroll
            for (int mt = 0; mt < 2; mt++) {
                int row = warpm * 32 + mt * 16 + a_row_off;
                uint32_t ad = smem_u32(&sAh[row * ASTR + k0 + a_col_off]);
                LDSM_X4(ah[mt][0], ah[mt][1], ah[mt][2], ah[mt][3], ad);
                uint32_t ad2 = smem_u32(&sAl[row * ASTR + k0 + a_col_off]);
                LDSM_X4(al[mt][0], al[mt][1], al[mt][2], al[mt][3], ad2);
            }
#pragma unroll
            for (int pr = 0; pr < 2; pr++) {
                int row = warpn * 32 + pr * 16 + b_row_off;
                uint32_t bd = smem_u32(&sBh[row * ASTR + k0 + b_col_off]);
                LDSM_X4(bh[2 * pr][0], bh[2 * pr][1], bh[2 * pr + 1][0],
                        bh[2 * pr + 1][1], bd);
                uint32_t bd2 = smem_u32(&sBl[row * ASTR + k0 + b_col_off]);
                LDSM_X4(bl[2 * pr][0], bl[2 * pr][1], bl[2 * pr + 1][0],
                        bl[2 * pr + 1][1], bd2);
            }
#pragma unroll
            for (int mt = 0; mt < 2; mt++)
#pragma unroll
                for (int t4 = 0; t4 < 4; t4++) {
                    MMA_BF16(acc[mt][t4], ah[mt], bh[t4]);
                    MMA_BF16(acc[mt][t4], al[mt], bh[t4]);
                    MMA_BF16(acc[mt][t4], ah[mt], bl[t4]);
                }
        }

        const int qrow = lane >> 2;
        const int qcol = (lane & 3) * 2;
#pragma unroll
        for (int mt = 0; mt < 2; mt++) {
#pragma unroll
            for (int t4 = 0; t4 < 4; t4++) {
                const int col = nt * 64 + warpn * 32 + t4 * 8 + qcol;
                const float b0 = bias[col], b1 = bias[col + 1];
                const int r0 = m_blk + warpm * 32 + mt * 16 + qrow;
                float v00 = acc[mt][t4][0] + b0, v01 = acc[mt][t4][1] + b1;
                float v10 = acc[mt][t4][2] + b0, v11 = acc[mt][t4][3] + b1;
                if (mode == 1) {
                    *reinterpret_cast<float2*>(&out[(size_t)r0 * CDIM + col]) =
                        make_float2(v00, v01);
                    *reinterpret_cast<float2*>(&out[(size_t)(r0 + 8) * CDIM + col]) =
                        make_float2(v10, v11);
                } else {
                    const int t = col / CDIM;
                    const int rem = col - t * CDIM;
                    const int hh = rem >> 5, dd = rem & 31;
                    const int bi0 = r0 / LTOK, l0 = r0 - bi0 * LTOK;
                    const int r1 = r0 + 8;
                    const int bi1 = r1 / LTOK, l1 = r1 - bi1 * LTOK;
                    const size_t o0 = ((size_t)(bi0 * HEADS + hh) * LTOK + l0) * HD + dd;
                    const size_t o1 = ((size_t)(bi1 * HEADS + hh) * LTOK + l1) * HD + dd;
                    __half ha, la, hb, lb, hc, lc, hd_, ld_;
                    if (t == 0) {
                        hsplit(v00 * QK_SCALE, ha, la); hsplit(v01 * QK_SCALE, hb, lb);
                        hsplit(v10 * QK_SCALE, hc, lc); hsplit(v11 * QK_SCALE, hd_, ld_);
                        *reinterpret_cast<__half2*>(g_Qh + o0) = __halves2half2(ha, hb);
                        *reinterpret_cast<__half2*>(g_Ql + o0) = __halves2half2(la, lb);
                        *reinterpret_cast<__half2*>(g_Qh + o1) = __halves2half2(hc, hd_);
                        *reinterpret_cast<__half2*>(g_Ql + o1) = __halves2half2(lc, ld_);
                    } else if (t == 1) {
                        hsplit(v00, ha, la); hsplit(v01, hb, lb);
                        hsplit(v10, hc, lc); hsplit(v11, hd_, ld_);
                        *reinterpret_cast<__half2*>(g_Kh + o0) = __halves2half2(ha, hb);
                        *reinterpret_cast<__half2*>(g_Kl + o0) = __halves2half2(la, lb);
                        *reinterpret_cast<__half2*>(g_Kh + o1) = __halves2half2(hc, hd_);
                        *reinterpret_cast<__half2*>(g_Kl + o1) = __halves2half2(lc, ld_);
                    } else {
                        hsplit(v00, ha, la); hsplit(v01, hb, lb);
                        hsplit(v10, hc, lc); hsplit(v11, hd_, ld_);
                        *reinterpret_cast<__half2*>(g_Vh + o0) = __halves2half2(ha, hb);
                        *reinterpret_cast<__half2*>(g_Vl + o0) = __halves2half2(la, lb);
                        *reinterpret_cast<__half2*>(g_Vh + o1) = __halves2half2(hc, hd_);
                        *reinterpret_cast<__half2*>(g_Vl + o1) = __halves2half2(lc, ld_);
                    }
                }
            }
        }
        __syncthreads();
    }
}

// ---------------------------------------------------------------------------
// K2: tensor-core attention. CTA = (window, head), 256 threads (8 warps).
//   S = QK^T (fp16 split, 3 passes) -> SMEM fp32 -> softmax(+bias+mask)
//   -> P fp16 -> O = P@V (V fp16 split, 2 passes) -> bf16-split ctx.
// ---------------------------------------------------------------------------
#define QSTR 40     // fp16 stride for Q/K [144][40]
#define VTSTR 152   // Vt [32][152] fp16
#define SSTR 148    // S fp32 [144][148]
#define PSTR 152    // P fp16 [144][152]
#define ATTN_SMEM (4 * 144 * QSTR * 2 + 2 * 32 * VTSTR * 2 + 144 * SSTR * 4 + 144 * PSTR * 2)

__global__ __launch_bounds__(256) void attn_mma_kernel(const float* __restrict__ mask) {
    extern __shared__ __align__(16) char sraw[];
    __half* sQh = reinterpret_cast<__half*>(sraw);
    __half* sQl = sQh + 144 * QSTR;
    __half* sKh = sQl + 144 * QSTR;
    __half* sKl = sKh + 144 * QSTR;
    __half* sVh = sKl + 144 * QSTR;          // [32][VTSTR] (transposed)
    __half* sVl = sVh + 32 * VTSTR;
    float*  sS  = reinterpret_cast<float*>(sVl + 32 * VTSTR);   // [144][SSTR]
    __half* sP  = reinterpret_cast<__half*>(sS + 144 * SSTR);   // [144][PSTR]

    const int bh = blockIdx.x;
    const int b = bh / HEADS, h = bh % HEADS;
    const int nw = b / WWINS;
    const int tid = threadIdx.x;
    const int warp = tid >> 5, lane = tid & 31;
    const size_t base = (size_t)bh * (LTOK * HD);

    // ---- stage Q/K (row-major) and V (transposed) ----
    for (int c = tid; c < 576; c += 256) {
        int l = c >> 2, dp = (c & 3) * 8;
        *reinterpret_cast<uint4*>(&sQh[l * QSTR + dp]) =
            *reinterpret_cast<const uint4*>(&g_Qh[base + l * 32 + dp]);
        *reinterpret_cast<uint4*>(&sQl[l * QSTR + dp]) =
            *reinterpret_cast<const uint4*>(&g_Ql[base + l * 32 + dp]);
        *reinterpret_cast<uint4*>(&sKh[l * QSTR + dp]) =
            *reinterpret_cast<const uint4*>(&g_Kh[base + l * 32 + dp]);
        *reinterpret_cast<uint4*>(&sKl[l * QSTR + dp]) =
            *reinterpret_cast<const uint4*>(&g_Kl[base + l * 32 + dp]);
    }
    for (int i = tid; i < 2304; i += 256) {
        int l = i >> 4, d2 = (i & 15) * 2;
        __half2 vh = *reinterpret_cast<const __half2*>(&g_Vh[base + l * 32 + d2]);
        __half2 vl = *reinterpret_cast<const __half2*>(&g_Vl[base + l * 32 + d2]);
        sVh[d2 * VTSTR + l] = __low2half(vh);
        sVh[(d2 + 1) * VTSTR + l] = __high2half(vh);
        sVl[d2 * VTSTR + l] = __low2half(vl);
        sVl[(d2 + 1) * VTSTR + l] = __high2half(vl);
    }
    __syncthreads();

    const int lr = lane & 7, sel = lane >> 3;
    const int arow = lr + (sel & 1) * 8, acol = (sel >> 1) * 8;
    const int brow = lr + (sel >> 1) * 8, bcol = (sel & 1) * 8;

    // ---- S = Q @ K^T : 81 (m16,n16) blocks over 8 warps ----
    for (int blk = warp; blk < 81; blk += 8) {
        const int mt = blk / 9, nt = blk % 9;
        float c0[4] = {0, 0, 0, 0}, c1[4] = {0, 0, 0, 0};
#pragma unroll
        for (int ks = 0; ks < 2; ks++) {
            uint32_t qh[4], ql[4], kh[4], kl[4];
            LDSM_X4(qh[0], qh[1], qh[2], qh[3],
                    smem_u32(&sQh[(mt * 16 + arow) * QSTR + ks * 16 + acol]));
            LDSM_X4(ql[0], ql[1], ql[2], ql[3],
                    smem_u32(&sQl[(mt * 16 + arow) * QSTR + ks * 16 + acol]));
            LDSM_X4(kh[0], kh[1], kh[2], kh[3],
                    smem_u32(&sKh[(nt * 16 + brow) * QSTR + ks * 16 + bcol]));
            LDSM_X4(kl[0], kl[1], kl[2], kl[3],
                    smem_u32(&sKl[(nt * 16 + brow) * QSTR + ks * 16 + bcol]));
            MMA_F16(c0, qh, kh + 0); MMA_F16(c1, qh, kh + 2);
            MMA_F16(c0, ql, kh + 0); MMA_F16(c1, ql, kh + 2);
            MMA_F16(c0, qh, kl + 0); MMA_F16(c1, qh, kl + 2);
        }
        const int r0 = mt * 16 + (lane >> 2);
        const int cc = nt * 16 + (lane & 3) * 2;
        *reinterpret_cast<float2*>(&sS[r0 * SSTR + cc]) = make_float2(c0[0], c0[1]);
        *reinterpret_cast<float2*>(&sS[(r0 + 8) * SSTR + cc]) = make_float2(c0[2], c0[3]);
        *reinterpret_cast<float2*>(&sS[r0 * SSTR + cc + 8]) = make_float2(c1[0], c1[1]);
        *reinterpret_cast<float2*>(&sS[(r0 + 8) * SSTR + cc + 8]) = make_float2(c1[2], c1[3]);
    }
    __syncthreads();

    // ---- softmax rows (18 per warp), add bias + mask from gmem ----
    const float* biasrow = g_bias + (size_t)(nw * HEADS + h) * (LTOK * LTOK);
    const float* maskrow = mask + (size_t)b * (LTOK * LTOK);
    for (int r = 0; r < 18; r++) {
        const int row = warp * 18 + r;
        float v[5];
#pragma unroll
        for (int j = 0; j < 5; j++) {
            int m = lane + 32 * j;
            v[j] = (m < LTOK)
                       ? sS[row * SSTR + m] + biasrow[row * LTOK + m] +
                             maskrow[row * LTOK + m]
                       : -1e30f;
        }
        float mx = v[0];
#pragma unroll
        for (int j = 1; j < 5; j++) mx = fmaxf(mx, v[j]);
#pragma unroll
        for (int off = 16; off; off >>= 1)
            mx = fmaxf(mx, __shfl_xor_sync(0xffffffffu, mx, off));
        float e[5], s = 0.f;
#pragma unroll
        for (int j = 0; j < 5; j++) {
            e[j] = (lane + 32 * j < LTOK) ? __expf(v[j] - mx) : 0.f;
            s += e[j];
        }
#pragma unroll
        for (int off = 16; off; off >>= 1)
            s += __shfl_xor_sync(0xffffffffu, s, off);
        const float inv = 1.f / s;
#pragma unroll
        for (int j = 0; j < 5; j++) {
            int m = lane + 32 * j;
            if (m < LTOK) sP[row * PSTR + m] = __float2half(e[j] * inv);
        }
    }
    __syncthreads();

    // ---- O = P @ V : 18 (m16,n16) blocks over 8 warps ----
    for (int blk = warp; blk < 18; blk += 8) {
        const int mt = blk >> 1, nt = blk & 1;
        float c0[4] = {0, 0, 0, 0}, c1[4] = {0, 0, 0, 0};
#pragma unroll 3
        for (int ks = 0; ks < 9; ks++) {
            uint32_t p[4], vh[4], vl[4];
            LDSM_X4(p[0], p[1], p[2], p[3],
                    smem_u32(&sP[(mt * 16 + arow) * PSTR + ks * 16 + acol]));
            LDSM_X4(vh[0], vh[1], vh[2], vh[3],
                    smem_u32(&sVh[(nt * 16 + brow) * VTSTR + ks * 16 + bcol]));
            LDSM_X4(vl[0], vl[1], vl[2], vl[3],
                    smem_u32(&sVl[(nt * 16 + brow) * VTSTR + ks * 16 + bcol]));
            MMA_F16(c0, p, vh + 0); MMA_F16(c1, p, vh + 2);
            MMA_F16(c0, p, vl + 0); MMA_F16(c1, p, vl + 2);
        }
        const int l0 = mt * 16 + (lane >> 2);
        const int d0 = nt * 16 + (lane & 3) * 2;
#pragma unroll
        for (int half_ = 0; half_ < 2; half_++) {
            const int l = l0 + half_ * 8;
            const float* cp0 = half_ ? (c0 + 2) : c0;
            const float* cp1 = half_ ? (c1 + 2) : c1;
            const size_t off = ((size_t)b * LTOK + l) * CDIM + h * HD;
            __nv_bfloat16 h0, l0b, h1, l1b;
            bsplit(cp0[0], h0, l0b); bsplit(cp0[1], h1, l1b);
            *reinterpret_cast<__nv_bfloat162*>(&g_CtxH[off + d0]) =
                __halves2bfloat162(h0, h1);
            *reinterpret_cast<__nv_bfloat162*>(&g_CtxL[off + d0]) =
                __halves2bfloat162(l0b, l1b);
            bsplit(cp1[0], h0, l0b); bsplit(cp1[1], h1, l1b);
            *reinterpret_cast<__nv_bfloat162*>(&g_CtxH[off + d0 + 8]) =
                __halves2bfloat162(h0, h1);
            *reinterpret_cast<__nv_bfloat162*>(&g_CtxL[off + d0 + 8]) =
                __halves2bfloat162(l0b, l1b);
        }
    }
}

// ---------------------------------------------------------------------------
extern "C" void kernel_launch(void* const* d_in, const int* in_sizes, int n_in,
                              void* d_out, int out_size) {
    const float* x    = (const float*)d_in[0];
    const float* mask = (const float*)d_in[1];
    const float* W1   = (const float*)d_in[2];
    const float* b1   = (const float*)d_in[3];
    const float* W2   = (const float*)d_in[4];
    const float* b2   = (const float*)d_in[5];
    const float* btab = (const float*)d_in[6];
    const int*   pidx = (const int*)d_in[7];
    float* out = (float*)d_out;
    (void)in_sizes; (void)n_in; (void)out_size;

    cudaFuncSetAttribute(mma_gemm_kernel,
                         cudaFuncAttributeMaxDynamicSharedMemorySize, GEMM_SMEM);
    cudaFuncSetAttribute(attn_mma_kernel,
                         cudaFuncAttributeMaxDynamicSharedMemorySize, ATTN_SMEM);

    __nv_bfloat16 *xh, *xl, *ch, *cl, *w1h, *w1l, *w2h, *w2l;
    cudaGetSymbolAddress((void**)&xh, g_Xh);
    cudaGetSymbolAddress((void**)&xl, g_Xl);
    cudaGetSymbolAddress((void**)&ch, g_CtxH);
    cudaGetSymbolAddress((void**)&cl, g_CtxL);
    cudaGetSymbolAddress((void**)&w1h, g_W1h);
    cudaGetSymbolAddress((void**)&w1l, g_W1l);
    cudaGetSymbolAddress((void**)&w2h, g_W2h);
    cudaGetSymbolAddress((void**)&w2l, g_W2l);

    const int n4 = MTOT * CDIM / 4;
    splitX_kernel<<<(n4 + 255) / 256, 256>>>(x, xh, xl, n4);
    splitW_kernel<<<(576 * 192 + 255) / 256, 256>>>(W1, w1h, w1l, 576);
    splitW_kernel<<<(192 * 192 + 255) / 256, 256>>>(W2, w2h, w2l, 192);
    bias_gather_kernel<<<NW * HEADS * 4, 256>>>(btab, pidx);

    mma_gemm_kernel<<<MTOT / 128, 256, GEMM_SMEM>>>(xh, xl, w1h, w1l, b1, 9, 0, nullptr);
    attn_mma_kernel<<<NWIN * HEADS, 256, ATTN_SMEM>>>(mask);
    mma_gemm_kernel<<<MTOT / 128, 256, GEMM_SMEM>>>(ch, cl, w2h, w2l, b2, 3, 1, out);
}

// round 5
// speedup vs baseline: 1.2560x; 1.2560x over previous
#include <cuda_runtime.h>
#include <cuda_bf16.h>
#include <cuda_fp16.h>
#include <cstdint>

// ---------------------------------------------------------------------------
// EarthAttention3D: B_=960, L=144, C=192, H=6, hd=32, NUM_WINDOWS=64, W_WINS=15
// Round 5: register-resident FlashAttention-style mma attention (no S/P SMEM
// round-trips, c-frag -> a-frag reuse); bf16-split projections via mma.sync.
// ---------------------------------------------------------------------------

#define NWIN   960
#define LTOK   144
#define CDIM   192
#define HEADS  6
#define HD     32
#define NW     64
#define WWINS  15
#define MTOT   (NWIN * LTOK)          // 138240
#define QK_SCALE 0.17677669529663687f

// ------------------------- scratch (device globals) ------------------------
__device__ float g_bias[NW * HEADS * LTOK * LTOK];
__device__ __half g_Qh[NWIN * HEADS * LTOK * HD];
__device__ __half g_Ql[NWIN * HEADS * LTOK * HD];
__device__ __half g_Kh[NWIN * HEADS * LTOK * HD];
__device__ __half g_Kl[NWIN * HEADS * LTOK * HD];
__device__ __half g_Vh[NWIN * HEADS * LTOK * HD];
__device__ __half g_Vl[NWIN * HEADS * LTOK * HD];
__device__ __nv_bfloat16 g_Xh[MTOT * CDIM];
__device__ __nv_bfloat16 g_Xl[MTOT * CDIM];
__device__ __nv_bfloat16 g_CtxH[MTOT * CDIM];
__device__ __nv_bfloat16 g_CtxL[MTOT * CDIM];
__device__ __nv_bfloat16 g_W1h[576 * 192];
__device__ __nv_bfloat16 g_W1l[576 * 192];
__device__ __nv_bfloat16 g_W2h[192 * 192];
__device__ __nv_bfloat16 g_W2l[192 * 192];

// ------------------------------ helpers ------------------------------------
__device__ __forceinline__ uint32_t smem_u32(const void* p) {
    uint32_t a;
    asm("{ .reg .u64 t; cvta.to.shared.u64 t, %1; cvt.u32.u64 %0, t; }"
        : "=r"(a) : "l"(p));
    return a;
}
__device__ __forceinline__ void bsplit(float v, __nv_bfloat16& h, __nv_bfloat16& l) {
    h = __float2bfloat16(v);
    l = __float2bfloat16(v - __bfloat162float(h));
}
__device__ __forceinline__ void hsplit(float v, __half& h, __half& l) {
    h = __float2half_rn(v);
    l = __float2half_rn(v - __half2float(h));
}
__device__ __forceinline__ uint32_t pack_h2(float a, float b) {
    __half2 t = __floats2half2_rn(a, b);
    return *reinterpret_cast<uint32_t*>(&t);
}

#define LDSM_X4(r0, r1, r2, r3, addr)                                          \
    asm volatile("ldmatrix.sync.aligned.m8n8.x4.shared.b16 {%0,%1,%2,%3}, [%4];" \
                 : "=r"(r0), "=r"(r1), "=r"(r2), "=r"(r3) : "r"(addr))

#define MMA_BF16(d, a, b)                                                      \
    asm volatile("mma.sync.aligned.m16n8k16.row.col.f32.bf16.bf16.f32 "        \
                 "{%0,%1,%2,%3}, {%4,%5,%6,%7}, {%8,%9}, {%0,%1,%2,%3};"       \
                 : "+f"((d)[0]), "+f"((d)[1]), "+f"((d)[2]), "+f"((d)[3])      \
                 : "r"((a)[0]), "r"((a)[1]), "r"((a)[2]), "r"((a)[3]),         \
                   "r"((b)[0]), "r"((b)[1]))

#define MMA_F16(d, a, b)                                                       \
    asm volatile("mma.sync.aligned.m16n8k16.row.col.f32.f16.f16.f32 "          \
                 "{%0,%1,%2,%3}, {%4,%5,%6,%7}, {%8,%9}, {%0,%1,%2,%3};"       \
                 : "+f"((d)[0]), "+f"((d)[1]), "+f"((d)[2]), "+f"((d)[3])      \
                 : "r"((a)[0]), "r"((a)[1]), "r"((a)[2]), "r"((a)[3]),         \
                   "r"((b)[0]), "r"((b)[1]))

// ---------------------------------------------------------------------------
// Prep: fp32 -> bf16 hi/lo splits
// ---------------------------------------------------------------------------
__global__ void splitX_kernel(const float* __restrict__ x,
                              __nv_bfloat16* __restrict__ h,
                              __nv_bfloat16* __restrict__ l, int n4) {
    int i = blockIdx.x * blockDim.x + threadIdx.x;
    if (i >= n4) return;
    float4 v = reinterpret_cast<const float4*>(x)[i];
    __nv_bfloat16 h0, h1, h2, h3, l0, l1, l2, l3;
    bsplit(v.x, h0, l0); bsplit(v.y, h1, l1);
    bsplit(v.z, h2, l2); bsplit(v.w, h3, l3);
    reinterpret_cast<__nv_bfloat162*>(h)[2 * i]     = __halves2bfloat162(h0, h1);
    reinterpret_cast<__nv_bfloat162*>(h)[2 * i + 1] = __halves2bfloat162(h2, h3);
    reinterpret_cast<__nv_bfloat162*>(l)[2 * i]     = __halves2bfloat162(l0, l1);
    reinterpret_cast<__nv_bfloat162*>(l)[2 * i + 1] = __halves2bfloat162(l2, l3);
}

__global__ void splitW_kernel(const float* __restrict__ W,
                              __nv_bfloat16* __restrict__ h,
                              __nv_bfloat16* __restrict__ l, int N) {
    int idx = blockIdx.x * blockDim.x + threadIdx.x;
    if (idx >= N * 192) return;
    int n = idx / 192, k = idx - n * 192;
    __nv_bfloat16 hh, ll;
    bsplit(W[(size_t)k * N + n], hh, ll);
    h[idx] = hh; l[idx] = ll;
}

// ---------------------------------------------------------------------------
// K0: bias gather (split 4x)
// ---------------------------------------------------------------------------
__global__ void bias_gather_kernel(const float* __restrict__ table,
                                   const int* __restrict__ pidx) {
    const int nwh = blockIdx.x >> 2;
    const int part = blockIdx.x & 3;
    const int nw = nwh / HEADS, h = nwh % HEADS;
    float* dst = g_bias + (size_t)nwh * (LTOK * LTOK);
    for (int i = part * 5184 + threadIdx.x; i < (part + 1) * 5184; i += 256) {
        int pi = pidx[i];
        dst[i] = table[((size_t)pi * NW + nw) * HEADS + h];
    }
}

// ---------------------------------------------------------------------------
// Split-bf16 GEMM via mma.sync (as R3/R4).
//   mode 0 -> fp16-split Q(scaled)/K/V head-major; mode 1 -> out fp32.
// ---------------------------------------------------------------------------
#define ASTR 200
#define GEMM_SMEM ((2 * 128 * ASTR + 2 * 64 * ASTR) * 2)  // 153600 B

__global__ __launch_bounds__(256) void mma_gemm_kernel(
    const __nv_bfloat16* __restrict__ Ah, const __nv_bfloat16* __restrict__ Al,
    const __nv_bfloat16* __restrict__ Bh, const __nv_bfloat16* __restrict__ Bl,
    const float* __restrict__ bias, int ntiles, int mode,
    float* __restrict__ out) {
    extern __shared__ __align__(16) __nv_bfloat16 sb[];
    __nv_bfloat16* sAh = sb;
    __nv_bfloat16* sAl = sb + 128 * ASTR;
    __nv_bfloat16* sBh = sb + 2 * 128 * ASTR;
    __nv_bfloat16* sBl = sBh + 64 * ASTR;

    const int tid = threadIdx.x;
    const int warp = tid >> 5, lane = tid & 31;
    const int warpm = warp >> 1, warpn = warp & 1;
    const int m_blk = blockIdx.x * 128;

    for (int i = tid; i < 128 * 24; i += 256) {
        int r = i / 24, c = (i % 24) * 8;
        *reinterpret_cast<uint4*>(&sAh[r * ASTR + c]) =
            *reinterpret_cast<const uint4*>(&Ah[(size_t)(m_blk + r) * 192 + c]);
        *reinterpret_cast<uint4*>(&sAl[r * ASTR + c]) =
            *reinterpret_cast<const uint4*>(&Al[(size_t)(m_blk + r) * 192 + c]);
    }
    __syncthreads();

    const int lr = lane & 7, sel = lane >> 3;
    const int a_row_off = lr + (sel & 1) * 8;
    const int a_col_off = (sel >> 1) * 8;
    const int b_row_off = lr + (sel >> 1) * 8;
    const int b_col_off = (sel & 1) * 8;

    for (int nt = 0; nt < ntiles; nt++) {
        for (int i = tid; i < 64 * 24; i += 256) {
            int r = i / 24, c = (i % 24) * 8;
            *reinterpret_cast<uint4*>(&sBh[r * ASTR + c]) =
                *reinterpret_cast<const uint4*>(&Bh[(size_t)(nt * 64 + r) * 192 + c]);
            *reinterpret_cast<uint4*>(&sBl[r * ASTR + c]) =
                *reinterpret_cast<const uint4*>(&Bl[(size_t)(nt * 64 + r) * 192 + c]);
        }
        __syncthreads();

        float acc[2][4][4];
#pragma unroll
        for (int mt = 0; mt < 2; mt++)
#pragma unroll
            for (int t4 = 0; t4 < 4; t4++)
#pragma unroll
                for (int j = 0; j < 4; j++) acc[mt][t4][j] = 0.f;

#pragma unroll 4
        for (int ks = 0; ks < 12; ks++) {
            const int k0 = ks * 16;
            uint32_t ah[2][4], al[2][4], bh[4][2], bl[4][2];
#pragma unroll
            for (int mt = 0; mt < 2; mt++) {
                int row = warpm * 32 + mt * 16 + a_row_off;
                uint32_t ad = smem_u32(&sAh[row * ASTR + k0 + a_col_off]);
                LDSM_X4(ah[mt][0], ah[mt][1], ah[mt][2], ah[mt][3], ad);
                uint32_t ad2 = smem_u32(&sAl[row * ASTR + k0 + a_col_off]);
                LDSM_X4(al[mt][0], al[mt][1], al[mt][2], al[mt][3], ad2);
            }
#pragma unroll
            for (int pr = 0; pr < 2; pr++) {
                int row = warpn * 32 + pr * 16 + b_row_off;
                uint32_t bd = smem_u32(&sBh[row * ASTR + k0 + b_col_off]);
                LDSM_X4(bh[2 * pr][0], bh[2 * pr][1], bh[2 * pr + 1][0],
                        bh[2 * pr + 1][1], bd);
                uint32_t bd2 = smem_u32(&sBl[row * ASTR + k0 + b_col_off]);
                LDSM_X4(bl[2 * pr][0], bl[2 * pr][1], bl[2 * pr + 1][0],
                        bl[2 * pr + 1][1], bd2);
            }
#pragma unroll
            for (int mt = 0; mt < 2; mt++)
#pragma unroll
                for (int t4 = 0; t4 < 4; t4++) {
                    MMA_BF16(acc[mt][t4], ah[mt], bh[t4]);
                    MMA_BF16(acc[mt][t4], al[mt], bh[t4]);
                    MMA_BF16(acc[mt][t4], ah[mt], bl[t4]);
                }
        }

        const int qrow = lane >> 2;
        const int qcol = (lane & 3) * 2;
#pragma unroll
        for (int mt = 0; mt < 2; mt++) {
#pragma unroll
            for (int t4 = 0; t4 < 4; t4++) {
                const int col = nt * 64 + warpn * 32 + t4 * 8 + qcol;
                const float b0 = bias[col], b1 = bias[col + 1];
                const int r0 = m_blk + warpm * 32 + mt * 16 + qrow;
                float v00 = acc[mt][t4][0] + b0, v01 = acc[mt][t4][1] + b1;
                float v10 = acc[mt][t4][2] + b0, v11 = acc[mt][t4][3] + b1;
                if (mode == 1) {
                    *reinterpret_cast<float2*>(&out[(size_t)r0 * CDIM + col]) =
                        make_float2(v00, v01);
                    *reinterpret_cast<float2*>(&out[(size_t)(r0 + 8) * CDIM + col]) =
                        make_float2(v10, v11);
                } else {
                    const int t = col / CDIM;
                    const int rem = col - t * CDIM;
                    const int hh = rem >> 5, dd = rem & 31;
                    const int bi0 = r0 / LTOK, l0 = r0 - bi0 * LTOK;
                    const int r1 = r0 + 8;
                    const int bi1 = r1 / LTOK, l1 = r1 - bi1 * LTOK;
                    const size_t o0 = ((size_t)(bi0 * HEADS + hh) * LTOK + l0) * HD + dd;
                    const size_t o1 = ((size_t)(bi1 * HEADS + hh) * LTOK + l1) * HD + dd;
                    __half ha, la, hb, lb, hc, lc, hd_, ld_;
                    if (t == 0) {
                        hsplit(v00 * QK_SCALE, ha, la); hsplit(v01 * QK_SCALE, hb, lb);
                        hsplit(v10 * QK_SCALE, hc, lc); hsplit(v11 * QK_SCALE, hd_, ld_);
                        *reinterpret_cast<__half2*>(g_Qh + o0) = __halves2half2(ha, hb);
                        *reinterpret_cast<__half2*>(g_Ql + o0) = __halves2half2(la, lb);
                        *reinterpret_cast<__half2*>(g_Qh + o1) = __halves2half2(hc, hd_);
                        *reinterpret_cast<__half2*>(g_Ql + o1) = __halves2half2(lc, ld_);
                    } else if (t == 1) {
                        hsplit(v00, ha, la); hsplit(v01, hb, lb);
                        hsplit(v10, hc, lc); hsplit(v11, hd_, ld_);
                        *reinterpret_cast<__half2*>(g_Kh + o0) = __halves2half2(ha, hb);
                        *reinterpret_cast<__half2*>(g_Kl + o0) = __halves2half2(la, lb);
                        *reinterpret_cast<__half2*>(g_Kh + o1) = __halves2half2(hc, hd_);
                        *reinterpret_cast<__half2*>(g_Kl + o1) = __halves2half2(lc, ld_);
                    } else {
                        hsplit(v00, ha, la); hsplit(v01, hb, lb);
                        hsplit(v10, hc, lc); hsplit(v11, hd_, ld_);
                        *reinterpret_cast<__half2*>(g_Vh + o0) = __halves2half2(ha, hb);
                        *reinterpret_cast<__half2*>(g_Vl + o0) = __halves2half2(la, lb);
                        *reinterpret_cast<__half2*>(g_Vh + o1) = __halves2half2(hc, hd_);
                        *reinterpret_cast<__half2*>(g_Vl + o1) = __halves2half2(lc, ld_);
                    }
                }
            }
        }
        __syncthreads();
    }
}

// ---------------------------------------------------------------------------
// K2: register-resident mma attention. CTA = (window, head), 288 threads
// (9 warps); warp w owns S rows [16w, 16w+16). One __syncthreads total.
// ---------------------------------------------------------------------------
#define QSTR 40     // fp16 stride Q/K [144][40]
#define VTSTR 152   // Vt [32][152] fp16
#define ATTN_SMEM (4 * 144 * QSTR * 2 + 2 * 32 * VTSTR * 2)   // 65536 B

__global__ __launch_bounds__(288, 1) void attn_mma_kernel(const float* __restrict__ mask) {
    extern __shared__ __align__(16) char sraw[];
    __half* sQh = reinterpret_cast<__half*>(sraw);
    __half* sQl = sQh + 144 * QSTR;
    __half* sKh = sQl + 144 * QSTR;
    __half* sKl = sKh + 144 * QSTR;
    __half* sVh = sKl + 144 * QSTR;          // [32][VTSTR] transposed
    __half* sVl = sVh + 32 * VTSTR;

    const int bh = blockIdx.x;
    const int b = bh / HEADS, h = bh % HEADS;
    const int nw = b / WWINS;
    const int tid = threadIdx.x;
    const int warp = tid >> 5, lane = tid & 31;
    const size_t base = (size_t)bh * (LTOK * HD);

    // ---- stage Q/K row-major, V transposed ----
    for (int c = tid; c < 576; c += 288) {
        int l = c >> 2, dp = (c & 3) * 8;
        *reinterpret_cast<uint4*>(&sQh[l * QSTR + dp]) =
            *reinterpret_cast<const uint4*>(&g_Qh[base + l * 32 + dp]);
        *reinterpret_cast<uint4*>(&sQl[l * QSTR + dp]) =
            *reinterpret_cast<const uint4*>(&g_Ql[base + l * 32 + dp]);
        *reinterpret_cast<uint4*>(&sKh[l * QSTR + dp]) =
            *reinterpret_cast<const uint4*>(&g_Kh[base + l * 32 + dp]);
        *reinterpret_cast<uint4*>(&sKl[l * QSTR + dp]) =
            *reinterpret_cast<const uint4*>(&g_Kl[base + l * 32 + dp]);
    }
    for (int i = tid; i < 2304; i += 288) {
        int l = i >> 4, d2 = (i & 15) * 2;
        __half2 vh = *reinterpret_cast<const __half2*>(&g_Vh[base + l * 32 + d2]);
        __half2 vl = *reinterpret_cast<const __half2*>(&g_Vl[base + l * 32 + d2]);
        sVh[d2 * VTSTR + l] = __low2half(vh);
        sVh[(d2 + 1) * VTSTR + l] = __high2half(vh);
        sVl[d2 * VTSTR + l] = __low2half(vl);
        sVl[(d2 + 1) * VTSTR + l] = __high2half(vl);
    }
    __syncthreads();

    const int lr = lane & 7, sel = lane >> 3;
    const int arow = lr + (sel & 1) * 8, acol = (sel >> 1) * 8;
    const int brow = lr + (sel >> 1) * 8, bcol = (sel & 1) * 8;
    const int g = lane >> 2, tg = lane & 3;

    // ---- Q fragments for this warp's 16-row strip (hoisted) ----
    uint32_t qh[2][4], ql[2][4];
#pragma unroll
    for (int ks = 0; ks < 2; ks++) {
        LDSM_X4(qh[ks][0], qh[ks][1], qh[ks][2], qh[ks][3],
                smem_u32(&sQh[(warp * 16 + arow) * QSTR + ks * 16 + acol]));
        LDSM_X4(ql[ks][0], ql[ks][1], ql[ks][2], ql[ks][3],
                smem_u32(&sQl[(warp * 16 + arow) * QSTR + ks * 16 + acol]));
    }

    // ---- S = QK^T: 18 n8-blocks of accumulators in registers ----
    float acc[18][4];
#pragma unroll
    for (int nb = 0; nb < 18; nb++)
#pragma unroll
        for (int j = 0; j < 4; j++) acc[nb][j] = 0.f;

#pragma unroll 3
    for (int nt = 0; nt < 9; nt++) {
#pragma unroll
        for (int ks = 0; ks < 2; ks++) {
            uint32_t kh[4], kl[4];
            LDSM_X4(kh[0], kh[1], kh[2], kh[3],
                    smem_u32(&sKh[(nt * 16 + brow) * QSTR + ks * 16 + bcol]));
            LDSM_X4(kl[0], kl[1], kl[2], kl[3],
                    smem_u32(&sKl[(nt * 16 + brow) * QSTR + ks * 16 + bcol]));
            MMA_F16(acc[2 * nt],     qh[ks], kh + 0);
            MMA_F16(acc[2 * nt + 1], qh[ks], kh + 2);
            MMA_F16(acc[2 * nt],     ql[ks], kh + 0);
            MMA_F16(acc[2 * nt + 1], ql[ks], kh + 2);
            MMA_F16(acc[2 * nt],     qh[ks], kl + 0);
            MMA_F16(acc[2 * nt + 1], qh[ks], kl + 2);
        }
    }

    // ---- add bias + mask, softmax in registers ----
    const float* biasrow = g_bias + (size_t)(nw * HEADS + h) * (LTOK * LTOK);
    const float* maskrow = mask + (size_t)b * (LTOK * LTOK);
    const int r0 = warp * 16 + g;
    const int r1 = r0 + 8;
#pragma unroll
    for (int nb = 0; nb < 18; nb++) {
        const int cc = nb * 8 + tg * 2;
        float2 b0 = *reinterpret_cast<const float2*>(&biasrow[r0 * LTOK + cc]);
        float2 m0 = *reinterpret_cast<const float2*>(&maskrow[r0 * LTOK + cc]);
        float2 b1 = *reinterpret_cast<const float2*>(&biasrow[r1 * LTOK + cc]);
        float2 m1 = *reinterpret_cast<const float2*>(&maskrow[r1 * LTOK + cc]);
        acc[nb][0] += b0.x + m0.x;
        acc[nb][1] += b0.y + m0.y;
        acc[nb][2] += b1.x + m1.x;
        acc[nb][3] += b1.y + m1.y;
    }
    float mx0 = -1e30f, mx1 = -1e30f;
#pragma unroll
    for (int nb = 0; nb < 18; nb++) {
        mx0 = fmaxf(mx0, fmaxf(acc[nb][0], acc[nb][1]));
        mx1 = fmaxf(mx1, fmaxf(acc[nb][2], acc[nb][3]));
    }
    mx0 = fmaxf(mx0, __shfl_xor_sync(0xffffffffu, mx0, 1));
    mx0 = fmaxf(mx0, __shfl_xor_sync(0xffffffffu, mx0, 2));
    mx1 = fmaxf(mx1, __shfl_xor_sync(0xffffffffu, mx1, 1));
    mx1 = fmaxf(mx1, __shfl_xor_sync(0xffffffffu, mx1, 2));
    float s0 = 0.f, s1 = 0.f;
#pragma unroll
    for (int nb = 0; nb < 18; nb++) {
        acc[nb][0] = __expf(acc[nb][0] - mx0);
        acc[nb][1] = __expf(acc[nb][1] - mx0);
        acc[nb][2] = __expf(acc[nb][2] - mx1);
        acc[nb][3] = __expf(acc[nb][3] - mx1);
        s0 += acc[nb][0] + acc[nb][1];
        s1 += acc[nb][2] + acc[nb][3];
    }
    s0 += __shfl_xor_sync(0xffffffffu, s0, 1);
    s0 += __shfl_xor_sync(0xffffffffu, s0, 2);
    s1 += __shfl_xor_sync(0xffffffffu, s1, 1);
    s1 += __shfl_xor_sync(0xffffffffu, s1, 2);
    const float inv0 = 1.f / s0, inv1 = 1.f / s1;

    // ---- O = P @ V: P fragments built directly from acc (c->a identity) ----
    float o[4][4];
#pragma unroll
    for (int nb = 0; nb < 4; nb++)
#pragma unroll
        for (int j = 0; j < 4; j++) o[nb][j] = 0.f;

#pragma unroll 3
    for (int ks = 0; ks < 9; ks++) {
        uint32_t a[4];
        a[0] = pack_h2(acc[2 * ks][0] * inv0, acc[2 * ks][1] * inv0);
        a[1] = pack_h2(acc[2 * ks][2] * inv1, acc[2 * ks][3] * inv1);
        a[2] = pack_h2(acc[2 * ks + 1][0] * inv0, acc[2 * ks + 1][1] * inv0);
        a[3] = pack_h2(acc[2 * ks + 1][2] * inv1, acc[2 * ks + 1][3] * inv1);
#pragma unroll
        for (int ntv = 0; ntv < 2; ntv++) {
            uint32_t vh[4], vl[4];
            LDSM_X4(vh[0], vh[1], vh[2], vh[3],
                    smem_u32(&sVh[(ntv * 16 + brow) * VTSTR + ks * 16 + bcol]));
            LDSM_X4(vl[0], vl[1], vl[2], vl[3],
                    smem_u32(&sVl[(ntv * 16 + brow) * VTSTR + ks * 16 + bcol]));
            MMA_F16(o[2 * ntv],     a, vh + 0);
            MMA_F16(o[2 * ntv + 1], a, vh + 2);
            MMA_F16(o[2 * ntv],     a, vl + 0);
            MMA_F16(o[2 * ntv + 1], a, vl + 2);
        }
    }

    // ---- epilogue: bf16-split ctx ----
#pragma unroll
    for (int nb = 0; nb < 4; nb++) {
        const int d0 = nb * 8 + tg * 2;
        const size_t off0 = ((size_t)b * LTOK + r0) * CDIM + h * HD + d0;
        const size_t off1 = ((size_t)b * LTOK + r1) * CDIM + h * HD + d0;
        __nv_bfloat16 h0, l0b, h1, l1b;
        bsplit(o[nb][0], h0, l0b); bsplit(o[nb][1], h1, l1b);
        *reinterpret_cast<__nv_bfloat162*>(&g_CtxH[off0]) = __halves2bfloat162(h0, h1);
        *reinterpret_cast<__nv_bfloat162*>(&g_CtxL[off0]) = __halves2bfloat162(l0b, l1b);
        bsplit(o[nb][2], h0, l0b); bsplit(o[nb][3], h1, l1b);
        *reinterpret_cast<__nv_bfloat162*>(&g_CtxH[off1]) = __halves2bfloat162(h0, h1);
        *reinterpret_cast<__nv_bfloat162*>(&g_CtxL[off1]) = __halves2bfloat162(l0b, l1b);
    }
}

// ---------------------------------------------------------------------------
extern "C" void kernel_launch(void* const* d_in, const int* in_sizes, int n_in,
                              void* d_out, int out_size) {
    const float* x    = (const float*)d_in[0];
    const float* mask = (const float*)d_in[1];
    const float* W1   = (const float*)d_in[2];
    const float* b1   = (const float*)d_in[3];
    const float* W2   = (const float*)d_in[4];
    const float* b2   = (const float*)d_in[5];
    const float* btab = (const float*)d_in[6];
    const int*   pidx = (const int*)d_in[7];
    float* out = (float*)d_out;
    (void)in_sizes; (void)n_in; (void)out_size;

    cudaFuncSetAttribute(mma_gemm_kernel,
                         cudaFuncAttributeMaxDynamicSharedMemorySize, GEMM_SMEM);
    cudaFuncSetAttribute(attn_mma_kernel,
                         cudaFuncAttributeMaxDynamicSharedMemorySize, ATTN_SMEM);

    __nv_bfloat16 *xh, *xl, *ch, *cl, *w1h, *w1l, *w2h, *w2l;
    cudaGetSymbolAddress((void**)&xh, g_Xh);
    cudaGetSymbolAddress((void**)&xl, g_Xl);
    cudaGetSymbolAddress((void**)&ch, g_CtxH);
    cudaGetSymbolAddress((void**)&cl, g_CtxL);
    cudaGetSymbolAddress((void**)&w1h, g_W1h);
    cudaGetSymbolAddress((void**)&w1l, g_W1l);
    cudaGetSymbolAddress((void**)&w2h, g_W2h);
    cudaGetSymbolAddress((void**)&w2l, g_W2l);

    const int n4 = MTOT * CDIM / 4;
    splitX_kernel<<<(n4 + 255) / 256, 256>>>(x, xh, xl, n4);
    splitW_kernel<<<(576 * 192 + 255) / 256, 256>>>(W1, w1h, w1l, 576);
    splitW_kernel<<<(192 * 192 + 255) / 256, 256>>>(W2, w2h, w2l, 192);
    bias_gather_kernel<<<NW * HEADS * 4, 256>>>(btab, pidx);

    mma_gemm_kernel<<<MTOT / 128, 256, GEMM_SMEM>>>(xh, xl, w1h, w1l, b1, 9, 0, nullptr);
    attn_mma_kernel<<<NWIN * HEADS, 288, ATTN_SMEM>>>(mask);
    mma_gemm_kernel<<<MTOT / 128, 256, GEMM_SMEM>>>(ch, cl, w2h, w2l, b2, 3, 1, out);
}

// round 6
// speedup vs baseline: 1.4682x; 1.1689x over previous
#include <cuda_runtime.h>
#include <cuda_bf16.h>
#include <cuda_fp16.h>
#include <cstdint>

// ---------------------------------------------------------------------------
// EarthAttention3D: B_=960, L=144, C=192, H=6, hd=32, NUM_WINDOWS=64, W_WINS=15
// Round 6: fp16 2-pass split GEMMs (A-side split only) + 2-pass S, register-
// resident attention. Legacy-HMMA-throughput-bound -> minimize MMA count.
// ---------------------------------------------------------------------------

#define NWIN   960
#define LTOK   144
#define CDIM   192
#define HEADS  6
#define HD     32
#define NW     64
#define WWINS  15
#define MTOT   (NWIN * LTOK)          // 138240
#define QK_SCALE 0.17677669529663687f

// ------------------------- scratch (device globals) ------------------------
__device__ float g_bias[NW * HEADS * LTOK * LTOK];
__device__ float g_ctx[MTOT * CDIM];
__device__ __half g_Qh[NWIN * HEADS * LTOK * HD];
__device__ __half g_Ql[NWIN * HEADS * LTOK * HD];
__device__ __half g_Kh[NWIN * HEADS * LTOK * HD];
__device__ __half g_Vh[NWIN * HEADS * LTOK * HD];
__device__ __half g_Vl[NWIN * HEADS * LTOK * HD];
__device__ __half g_W1h[576 * 192];
__device__ __half g_W2h[192 * 192];

// ------------------------------ helpers ------------------------------------
__device__ __forceinline__ uint32_t smem_u32(const void* p) {
    uint32_t a;
    asm("{ .reg .u64 t; cvta.to.shared.u64 t, %1; cvt.u32.u64 %0, t; }"
        : "=r"(a) : "l"(p));
    return a;
}
__device__ __forceinline__ void hsplit(float v, __half& h, __half& l) {
    h = __float2half_rn(v);
    l = __float2half_rn(v - __half2float(h));
}
__device__ __forceinline__ uint32_t pack_h2(float a, float b) {
    __half2 t = __floats2half2_rn(a, b);
    return *reinterpret_cast<uint32_t*>(&t);
}

#define LDSM_X4(r0, r1, r2, r3, addr)                                          \
    asm volatile("ldmatrix.sync.aligned.m8n8.x4.shared.b16 {%0,%1,%2,%3}, [%4];" \
                 : "=r"(r0), "=r"(r1), "=r"(r2), "=r"(r3) : "r"(addr))

#define MMA_F16(d, a, b)                                                       \
    asm volatile("mma.sync.aligned.m16n8k16.row.col.f32.f16.f16.f32 "          \
                 "{%0,%1,%2,%3}, {%4,%5,%6,%7}, {%8,%9}, {%0,%1,%2,%3};"       \
                 : "+f"((d)[0]), "+f"((d)[1]), "+f"((d)[2]), "+f"((d)[3])      \
                 : "r"((a)[0]), "r"((a)[1]), "r"((a)[2]), "r"((a)[3]),         \
                   "r"((b)[0]), "r"((b)[1]))

// ---------------------------------------------------------------------------
// Prep: W [192][N] fp32 -> Wh [N][192] fp16 (transposed, hi only)
// ---------------------------------------------------------------------------
__global__ void splitW_kernel(const float* __restrict__ W,
                              __half* __restrict__ h, int N) {
    int idx = blockIdx.x * blockDim.x + threadIdx.x;
    if (idx >= N * 192) return;
    int n = idx / 192, k = idx - n * 192;
    h[idx] = __float2half_rn(W[(size_t)k * N + n]);
}

// ---------------------------------------------------------------------------
// K0: bias gather (split 4x)
// ---------------------------------------------------------------------------
__global__ void bias_gather_kernel(const float* __restrict__ table,
                                   const int* __restrict__ pidx) {
    const int nwh = blockIdx.x >> 2;
    const int part = blockIdx.x & 3;
    const int nw = nwh / HEADS, h = nwh % HEADS;
    float* dst = g_bias + (size_t)nwh * (LTOK * LTOK);
    for (int i = part * 5184 + threadIdx.x; i < (part + 1) * 5184; i += 256) {
        int pi = pidx[i];
        dst[i] = table[((size_t)pi * NW + nw) * HEADS + h];
    }
}

// ---------------------------------------------------------------------------
// fp16 2-pass GEMM: C[M,Ntot] = A[M,192] @ Wh[Ntot,192]^T + bias
//   A fp32 staged + hi/lo split in-kernel; B fp16 hi only.
//   mode 0 -> Qh/Ql (scaled), Kh, Vh/Vl head-major; mode 1 -> out fp32.
// ---------------------------------------------------------------------------
#define ASTR 200
#define GEMM_SMEM ((2 * 128 * ASTR + 64 * ASTR) * 2)  // 128000 B

__global__ __launch_bounds__(256) void mma_gemm_kernel(
    const float* __restrict__ A, const __half* __restrict__ Bh,
    const float* __restrict__ bias, int ntiles, int mode,
    float* __restrict__ out) {
    extern __shared__ __align__(16) __half sb[];
    __half* sAh = sb;                      // [128][ASTR]
    __half* sAl = sb + 128 * ASTR;
    __half* sBh = sb + 2 * 128 * ASTR;     // [64][ASTR]

    const int tid = threadIdx.x;
    const int warp = tid >> 5, lane = tid & 31;
    const int warpm = warp >> 1, warpn = warp & 1;
    const int m_blk = blockIdx.x * 128;

    // ---- stage A (fp32 -> fp16 hi/lo) ----
    for (int i = tid; i < 128 * 48; i += 256) {
        int r = i / 48, c4 = (i % 48) * 4;
        float4 v = *reinterpret_cast<const float4*>(&A[(size_t)(m_blk + r) * 192 + c4]);
        __half h0, l0, h1, l1, h2, l2, h3, l3;
        hsplit(v.x, h0, l0); hsplit(v.y, h1, l1);
        hsplit(v.z, h2, l2); hsplit(v.w, h3, l3);
        *reinterpret_cast<__half2*>(&sAh[r * ASTR + c4]) = __halves2half2(h0, h1);
        *reinterpret_cast<__half2*>(&sAh[r * ASTR + c4 + 2]) = __halves2half2(h2, h3);
        *reinterpret_cast<__half2*>(&sAl[r * ASTR + c4]) = __halves2half2(l0, l1);
        *reinterpret_cast<__half2*>(&sAl[r * ASTR + c4 + 2]) = __halves2half2(l2, l3);
    }
    __syncthreads();

    const int lr = lane & 7, sel = lane >> 3;
    const int a_row_off = lr + (sel & 1) * 8;
    const int a_col_off = (sel >> 1) * 8;
    const int b_row_off = lr + (sel >> 1) * 8;
    const int b_col_off = (sel & 1) * 8;

    for (int nt = 0; nt < ntiles; nt++) {
        for (int i = tid; i < 64 * 24; i += 256) {
            int r = i / 24, c = (i % 24) * 8;
            *reinterpret_cast<uint4*>(&sBh[r * ASTR + c]) =
                *reinterpret_cast<const uint4*>(&Bh[(size_t)(nt * 64 + r) * 192 + c]);
        }
        __syncthreads();

        float acc[2][4][4];
#pragma unroll
        for (int mt = 0; mt < 2; mt++)
#pragma unroll
            for (int t4 = 0; t4 < 4; t4++)
#pragma unroll
                for (int j = 0; j < 4; j++) acc[mt][t4][j] = 0.f;

#pragma unroll 4
        for (int ks = 0; ks < 12; ks++) {
            const int k0 = ks * 16;
            uint32_t ah[2][4], al[2][4], bh[4][2];
#pragma unroll
            for (int mt = 0; mt < 2; mt++) {
                int row = warpm * 32 + mt * 16 + a_row_off;
                LDSM_X4(ah[mt][0], ah[mt][1], ah[mt][2], ah[mt][3],
                        smem_u32(&sAh[row * ASTR + k0 + a_col_off]));
                LDSM_X4(al[mt][0], al[mt][1], al[mt][2], al[mt][3],
                        smem_u32(&sAl[row * ASTR + k0 + a_col_off]));
            }
#pragma unroll
            for (int pr = 0; pr < 2; pr++) {
                int row = warpn * 32 + pr * 16 + b_row_off;
                LDSM_X4(bh[2 * pr][0], bh[2 * pr][1], bh[2 * pr + 1][0],
                        bh[2 * pr + 1][1],
                        smem_u32(&sBh[row * ASTR + k0 + b_col_off]));
            }
#pragma unroll
            for (int mt = 0; mt < 2; mt++)
#pragma unroll
                for (int t4 = 0; t4 < 4; t4++) {
                    MMA_F16(acc[mt][t4], ah[mt], bh[t4]);
                    MMA_F16(acc[mt][t4], al[mt], bh[t4]);
                }
        }

        const int qrow = lane >> 2;
        const int qcol = (lane & 3) * 2;
#pragma unroll
        for (int mt = 0; mt < 2; mt++) {
#pragma unroll
            for (int t4 = 0; t4 < 4; t4++) {
                const int col = nt * 64 + warpn * 32 + t4 * 8 + qcol;
                const float b0 = bias[col], b1 = bias[col + 1];
                const int r0 = m_blk + warpm * 32 + mt * 16 + qrow;
                float v00 = acc[mt][t4][0] + b0, v01 = acc[mt][t4][1] + b1;
                float v10 = acc[mt][t4][2] + b0, v11 = acc[mt][t4][3] + b1;
                if (mode == 1) {
                    *reinterpret_cast<float2*>(&out[(size_t)r0 * CDIM + col]) =
                        make_float2(v00, v01);
                    *reinterpret_cast<float2*>(&out[(size_t)(r0 + 8) * CDIM + col]) =
                        make_float2(v10, v11);
                } else {
                    const int t = col / CDIM;
                    const int rem = col - t * CDIM;
                    const int hh = rem >> 5, dd = rem & 31;
                    const int bi0 = r0 / LTOK, l0 = r0 - bi0 * LTOK;
                    const int r1 = r0 + 8;
                    const int bi1 = r1 / LTOK, l1 = r1 - bi1 * LTOK;
                    const size_t o0 = ((size_t)(bi0 * HEADS + hh) * LTOK + l0) * HD + dd;
                    const size_t o1 = ((size_t)(bi1 * HEADS + hh) * LTOK + l1) * HD + dd;
                    if (t == 0) {
                        __half ha, la, hb, lb;
                        hsplit(v00 * QK_SCALE, ha, la); hsplit(v01 * QK_SCALE, hb, lb);
                        *reinterpret_cast<__half2*>(g_Qh + o0) = __halves2half2(ha, hb);
                        *reinterpret_cast<__half2*>(g_Ql + o0) = __halves2half2(la, lb);
                        hsplit(v10 * QK_SCALE, ha, la); hsplit(v11 * QK_SCALE, hb, lb);
                        *reinterpret_cast<__half2*>(g_Qh + o1) = __halves2half2(ha, hb);
                        *reinterpret_cast<__half2*>(g_Ql + o1) = __halves2half2(la, lb);
                    } else if (t == 1) {
                        *reinterpret_cast<__half2*>(g_Kh + o0) =
                            __floats2half2_rn(v00, v01);
                        *reinterpret_cast<__half2*>(g_Kh + o1) =
                            __floats2half2_rn(v10, v11);
                    } else {
                        __half ha, la, hb, lb;
                        hsplit(v00, ha, la); hsplit(v01, hb, lb);
                        *reinterpret_cast<__half2*>(g_Vh + o0) = __halves2half2(ha, hb);
                        *reinterpret_cast<__half2*>(g_Vl + o0) = __halves2half2(la, lb);
                        hsplit(v10, ha, la); hsplit(v11, hb, lb);
                        *reinterpret_cast<__half2*>(g_Vh + o1) = __halves2half2(ha, hb);
                        *reinterpret_cast<__half2*>(g_Vl + o1) = __halves2half2(la, lb);
                    }
                }
            }
        }
        __syncthreads();
    }
}

// ---------------------------------------------------------------------------
// K2: register-resident mma attention. CTA = (window, head), 288 threads.
//   S = (Qh+Ql)@Kh (2-pass), softmax in regs, O = P@(Vh+Vl), ctx fp32 out.
// ---------------------------------------------------------------------------
#define QSTR 40
#define VTSTR 152
#define ATTN_SMEM (3 * 144 * QSTR * 2 + 2 * 32 * VTSTR * 2)   // 54016 B

__global__ __launch_bounds__(288, 1) void attn_mma_kernel(const float* __restrict__ mask) {
    extern __shared__ __align__(16) char sraw[];
    __half* sQh = reinterpret_cast<__half*>(sraw);
    __half* sQl = sQh + 144 * QSTR;
    __half* sKh = sQl + 144 * QSTR;
    __half* sVh = sKh + 144 * QSTR;          // [32][VTSTR] transposed
    __half* sVl = sVh + 32 * VTSTR;

    const int bh = blockIdx.x;
    const int b = bh / HEADS, h = bh % HEADS;
    const int nw = b / WWINS;
    const int tid = threadIdx.x;
    const int warp = tid >> 5, lane = tid & 31;
    const size_t base = (size_t)bh * (LTOK * HD);

    for (int c = tid; c < 576; c += 288) {
        int l = c >> 2, dp = (c & 3) * 8;
        *reinterpret_cast<uint4*>(&sQh[l * QSTR + dp]) =
            *reinterpret_cast<const uint4*>(&g_Qh[base + l * 32 + dp]);
        *reinterpret_cast<uint4*>(&sQl[l * QSTR + dp]) =
            *reinterpret_cast<const uint4*>(&g_Ql[base + l * 32 + dp]);
        *reinterpret_cast<uint4*>(&sKh[l * QSTR + dp]) =
            *reinterpret_cast<const uint4*>(&g_Kh[base + l * 32 + dp]);
    }
    for (int i = tid; i < 2304; i += 288) {
        int l = i >> 4, d2 = (i & 15) * 2;
        __half2 vh = *reinterpret_cast<const __half2*>(&g_Vh[base + l * 32 + d2]);
        __half2 vl = *reinterpret_cast<const __half2*>(&g_Vl[base + l * 32 + d2]);
        sVh[d2 * VTSTR + l] = __low2half(vh);
        sVh[(d2 + 1) * VTSTR + l] = __high2half(vh);
        sVl[d2 * VTSTR + l] = __low2half(vl);
        sVl[(d2 + 1) * VTSTR + l] = __high2half(vl);
    }
    __syncthreads();

    const int lr = lane & 7, sel = lane >> 3;
    const int arow = lr + (sel & 1) * 8, acol = (sel >> 1) * 8;
    const int brow = lr + (sel >> 1) * 8, bcol = (sel & 1) * 8;
    const int g = lane >> 2, tg = lane & 3;

    uint32_t qh[2][4], ql[2][4];
#pragma unroll
    for (int ks = 0; ks < 2; ks++) {
        LDSM_X4(qh[ks][0], qh[ks][1], qh[ks][2], qh[ks][3],
                smem_u32(&sQh[(warp * 16 + arow) * QSTR + ks * 16 + acol]));
        LDSM_X4(ql[ks][0], ql[ks][1], ql[ks][2], ql[ks][3],
                smem_u32(&sQl[(warp * 16 + arow) * QSTR + ks * 16 + acol]));
    }

    float acc[18][4];
#pragma unroll
    for (int nb = 0; nb < 18; nb++)
#pragma unroll
        for (int j = 0; j < 4; j++) acc[nb][j] = 0.f;

#pragma unroll 3
    for (int nt = 0; nt < 9; nt++) {
#pragma unroll
        for (int ks = 0; ks < 2; ks++) {
            uint32_t kh[4];
            LDSM_X4(kh[0], kh[1], kh[2], kh[3],
                    smem_u32(&sKh[(nt * 16 + brow) * QSTR + ks * 16 + bcol]));
            MMA_F16(acc[2 * nt],     qh[ks], kh + 0);
            MMA_F16(acc[2 * nt + 1], qh[ks], kh + 2);
            MMA_F16(acc[2 * nt],     ql[ks], kh + 0);
            MMA_F16(acc[2 * nt + 1], ql[ks], kh + 2);
        }
    }

    const float* biasrow = g_bias + (size_t)(nw * HEADS + h) * (LTOK * LTOK);
    const float* maskrow = mask + (size_t)b * (LTOK * LTOK);
    const int r0 = warp * 16 + g;
    const int r1 = r0 + 8;
#pragma unroll
    for (int nb = 0; nb < 18; nb++) {
        const int cc = nb * 8 + tg * 2;
        float2 b0 = *reinterpret_cast<const float2*>(&biasrow[r0 * LTOK + cc]);
        float2 m0 = *reinterpret_cast<const float2*>(&maskrow[r0 * LTOK + cc]);
        float2 b1 = *reinterpret_cast<const float2*>(&biasrow[r1 * LTOK + cc]);
        float2 m1 = *reinterpret_cast<const float2*>(&maskrow[r1 * LTOK + cc]);
        acc[nb][0] += b0.x + m0.x;
        acc[nb][1] += b0.y + m0.y;
        acc[nb][2] += b1.x + m1.x;
        acc[nb][3] += b1.y + m1.y;
    }
    float mx0 = -1e30f, mx1 = -1e30f;
#pragma unroll
    for (int nb = 0; nb < 18; nb++) {
        mx0 = fmaxf(mx0, fmaxf(acc[nb][0], acc[nb][1]));
        mx1 = fmaxf(mx1, fmaxf(acc[nb][2], acc[nb][3]));
    }
    mx0 = fmaxf(mx0, __shfl_xor_sync(0xffffffffu, mx0, 1));
    mx0 = fmaxf(mx0, __shfl_xor_sync(0xffffffffu, mx0, 2));
    mx1 = fmaxf(mx1, __shfl_xor_sync(0xffffffffu, mx1, 1));
    mx1 = fmaxf(mx1, __shfl_xor_sync(0xffffffffu, mx1, 2));
    float s0 = 0.f, s1 = 0.f;
#pragma unroll
    for (int nb = 0; nb < 18; nb++) {
        acc[nb][0] = __expf(acc[nb][0] - mx0);
        acc[nb][1] = __expf(acc[nb][1] - mx0);
        acc[nb][2] = __expf(acc[nb][2] - mx1);
        acc[nb][3] = __expf(acc[nb][3] - mx1);
        s0 += acc[nb][0] + acc[nb][1];
        s1 += acc[nb][2] + acc[nb][3];
    }
    s0 += __shfl_xor_sync(0xffffffffu, s0, 1);
    s0 += __shfl_xor_sync(0xffffffffu, s0, 2);
    s1 += __shfl_xor_sync(0xffffffffu, s1, 1);
    s1 += __shfl_xor_sync(0xffffffffu, s1, 2);
    const float inv0 = 1.f / s0, inv1 = 1.f / s1;

    float o[4][4];
#pragma unroll
    for (int nb = 0; nb < 4; nb++)
#pragma unroll
        for (int j = 0; j < 4; j++) o[nb][j] = 0.f;

#pragma unroll 3
    for (int ks = 0; ks < 9; ks++) {
        uint32_t a[4];
        a[0] = pack_h2(acc[2 * ks][0] * inv0, acc[2 * ks][1] * inv0);
        a[1] = pack_h2(acc[2 * ks][2] * inv1, acc[2 * ks][3] * inv1);
        a[2] = pack_h2(acc[2 * ks + 1][0] * inv0, acc[2 * ks + 1][1] * inv0);
        a[3] = pack_h2(acc[2 * ks + 1][2] * inv1, acc[2 * ks + 1][3] * inv1);
#pragma unroll
        for (int ntv = 0; ntv < 2; ntv++) {
            uint32_t vh[4], vl[4];
            LDSM_X4(vh[0], vh[1], vh[2], vh[3],
                    smem_u32(&sVh[(ntv * 16 + brow) * VTSTR + ks * 16 + bcol]));
            LDSM_X4(vl[0], vl[1], vl[2], vl[3],
                    smem_u32(&sVl[(ntv * 16 + brow) * VTSTR + ks * 16 + bcol]));
            MMA_F16(o[2 * ntv],     a, vh + 0);
            MMA_F16(o[2 * ntv + 1], a, vh + 2);
            MMA_F16(o[2 * ntv],     a, vl + 0);
            MMA_F16(o[2 * ntv + 1], a, vl + 2);
        }
    }

#pragma unroll
    for (int nb = 0; nb < 4; nb++) {
        const int d0 = nb * 8 + tg * 2;
        const size_t off0 = ((size_t)b * LTOK + r0) * CDIM + h * HD + d0;
        const size_t off1 = ((size_t)b * LTOK + r1) * CDIM + h * HD + d0;
        *reinterpret_cast<float2*>(&g_ctx[off0]) = make_float2(o[nb][0], o[nb][1]);
        *reinterpret_cast<float2*>(&g_ctx[off1]) = make_float2(o[nb][2], o[nb][3]);
    }
}

// ---------------------------------------------------------------------------
extern "C" void kernel_launch(void* const* d_in, const int* in_sizes, int n_in,
                              void* d_out, int out_size) {
    const float* x    = (const float*)d_in[0];
    const float* mask = (const float*)d_in[1];
    const float* W1   = (const float*)d_in[2];
    const float* b1   = (const float*)d_in[3];
    const float* W2   = (const float*)d_in[4];
    const float* b2   = (const float*)d_in[5];
    const float* btab = (const float*)d_in[6];
    const int*   pidx = (const int*)d_in[7];
    float* out = (float*)d_out;
    (void)in_sizes; (void)n_in; (void)out_size;

    cudaFuncSetAttribute(mma_gemm_kernel,
                         cudaFuncAttributeMaxDynamicSharedMemorySize, GEMM_SMEM);
    cudaFuncSetAttribute(attn_mma_kernel,
                         cudaFuncAttributeMaxDynamicSharedMemorySize, ATTN_SMEM);

    __half *w1h, *w2h;
    float* ctx;
    cudaGetSymbolAddress((void**)&w1h, g_W1h);
    cudaGetSymbolAddress((void**)&w2h, g_W2h);
    cudaGetSymbolAddress((void**)&ctx, g_ctx);

    splitW_kernel<<<(576 * 192 + 255) / 256, 256>>>(W1, w1h, 576);
    splitW_kernel<<<(192 * 192 + 255) / 256, 256>>>(W2, w2h, 192);
    bias_gather_kernel<<<NW * HEADS * 4, 256>>>(btab, pidx);

    mma_gemm_kernel<<<MTOT / 128, 256, GEMM_SMEM>>>(x, w1h, b1, 9, 0, nullptr);
    attn_mma_kernel<<<NWIN * HEADS, 288, ATTN_SMEM>>>(mask);
    mma_gemm_kernel<<<MTOT / 128, 256, GEMM_SMEM>>>(ctx, w2h, b2, 3, 1, out);
}

// round 7
// speedup vs baseline: 2.0351x; 1.3862x over previous
#include <cuda_runtime.h>
#include <cuda_bf16.h>
#include <cuda_fp16.h>
#include <cstdint>

// ---------------------------------------------------------------------------
// EarthAttention3D: B_=960, L=144, C=192, H=6, hd=32, NUM_WINDOWS=64, W_WINS=15
// Round 7: occupancy fix. GEMM splits B (W) hi/lo, A plain fp16 -> 102.4KB
// SMEM -> 2 CTA/SM. Attention allowed 2 CTA/SM. 2-pass MMA everywhere.
// ---------------------------------------------------------------------------

#define NWIN   960
#define LTOK   144
#define CDIM   192
#define HEADS  6
#define HD     32
#define NW     64
#define WWINS  15
#define MTOT   (NWIN * LTOK)          // 138240
#define QK_SCALE 0.17677669529663687f

// ------------------------- scratch (device globals) ------------------------
__device__ float g_bias[NW * HEADS * LTOK * LTOK];
__device__ float g_ctx[MTOT * CDIM];
__device__ __half g_Qh[NWIN * HEADS * LTOK * HD];
__device__ __half g_Ql[NWIN * HEADS * LTOK * HD];
__device__ __half g_Kh[NWIN * HEADS * LTOK * HD];
__device__ __half g_Vh[NWIN * HEADS * LTOK * HD];
__device__ __half g_Vl[NWIN * HEADS * LTOK * HD];
__device__ __half g_W1h[576 * 192];
__device__ __half g_W1l[576 * 192];
__device__ __half g_W2h[192 * 192];
__device__ __half g_W2l[192 * 192];

// ------------------------------ helpers ------------------------------------
__device__ __forceinline__ uint32_t smem_u32(const void* p) {
    uint32_t a;
    asm("{ .reg .u64 t; cvta.to.shared.u64 t, %1; cvt.u32.u64 %0, t; }"
        : "=r"(a) : "l"(p));
    return a;
}
__device__ __forceinline__ void hsplit(float v, __half& h, __half& l) {
    h = __float2half_rn(v);
    l = __float2half_rn(v - __half2float(h));
}
__device__ __forceinline__ uint32_t pack_h2(float a, float b) {
    __half2 t = __floats2half2_rn(a, b);
    return *reinterpret_cast<uint32_t*>(&t);
}

#define LDSM_X4(r0, r1, r2, r3, addr)                                          \
    asm volatile("ldmatrix.sync.aligned.m8n8.x4.shared.b16 {%0,%1,%2,%3}, [%4];" \
                 : "=r"(r0), "=r"(r1), "=r"(r2), "=r"(r3) : "r"(addr))

#define MMA_F16(d, a, b)                                                       \
    asm volatile("mma.sync.aligned.m16n8k16.row.col.f32.f16.f16.f32 "          \
                 "{%0,%1,%2,%3}, {%4,%5,%6,%7}, {%8,%9}, {%0,%1,%2,%3};"       \
                 : "+f"((d)[0]), "+f"((d)[1]), "+f"((d)[2]), "+f"((d)[3])      \
                 : "r"((a)[0]), "r"((a)[1]), "r"((a)[2]), "r"((a)[3]),         \
                   "r"((b)[0]), "r"((b)[1]))

// ---------------------------------------------------------------------------
// Prep: W [192][N] fp32 -> [N][192] fp16 hi/lo (transposed)
// ---------------------------------------------------------------------------
__global__ void splitW_kernel(const float* __restrict__ W,
                              __half* __restrict__ h, __half* __restrict__ l,
                              int N) {
    int idx = blockIdx.x * blockDim.x + threadIdx.x;
    if (idx >= N * 192) return;
    int n = idx / 192, k = idx - n * 192;
    __half hh, ll;
    hsplit(W[(size_t)k * N + n], hh, ll);
    h[idx] = hh; l[idx] = ll;
}

// ---------------------------------------------------------------------------
// K0: bias gather (split 4x)
// ---------------------------------------------------------------------------
__global__ void bias_gather_kernel(const float* __restrict__ table,
                                   const int* __restrict__ pidx) {
    const int nwh = blockIdx.x >> 2;
    const int part = blockIdx.x & 3;
    const int nw = nwh / HEADS, h = nwh % HEADS;
    float* dst = g_bias + (size_t)nwh * (LTOK * LTOK);
    for (int i = part * 5184 + threadIdx.x; i < (part + 1) * 5184; i += 256) {
        int pi = pidx[i];
        dst[i] = table[((size_t)pi * NW + nw) * HEADS + h];
    }
}

// ---------------------------------------------------------------------------
// fp16 2-pass GEMM (B split): C[M,Ntot] = A[M,192] @ (Bh+Bl)[Ntot,192]^T + bias
//   A fp32 -> fp16 staged in-kernel (single buffer). 102.4KB SMEM, 2 CTA/SM.
//   mode 0 -> Qh/Ql (scaled), Kh, Vh/Vl head-major; mode 1 -> out fp32.
// ---------------------------------------------------------------------------
#define ASTR 200
#define GEMM_SMEM ((128 * ASTR + 2 * 64 * ASTR) * 2)  // 102400 B

__global__ __launch_bounds__(256, 2) void mma_gemm_kernel(
    const float* __restrict__ A, const __half* __restrict__ Bh,
    const __half* __restrict__ Bl, const float* __restrict__ bias,
    int ntiles, int mode, float* __restrict__ out) {
    extern __shared__ __align__(16) __half sb[];
    __half* sA  = sb;                      // [128][ASTR]
    __half* sBh = sb + 128 * ASTR;         // [64][ASTR]
    __half* sBl = sBh + 64 * ASTR;

    const int tid = threadIdx.x;
    const int warp = tid >> 5, lane = tid & 31;
    const int warpm = warp >> 1, warpn = warp & 1;
    const int m_blk = blockIdx.x * 128;

    // ---- stage A (fp32 -> fp16) ----
    for (int i = tid; i < 128 * 48; i += 256) {
        int r = i / 48, c4 = (i % 48) * 4;
        float4 v = *reinterpret_cast<const float4*>(&A[(size_t)(m_blk + r) * 192 + c4]);
        *reinterpret_cast<__half2*>(&sA[r * ASTR + c4]) = __floats2half2_rn(v.x, v.y);
        *reinterpret_cast<__half2*>(&sA[r * ASTR + c4 + 2]) = __floats2half2_rn(v.z, v.w);
    }
    __syncthreads();

    const int lr = lane & 7, sel = lane >> 3;
    const int a_row_off = lr + (sel & 1) * 8;
    const int a_col_off = (sel >> 1) * 8;
    const int b_row_off = lr + (sel >> 1) * 8;
    const int b_col_off = (sel & 1) * 8;

    for (int nt = 0; nt < ntiles; nt++) {
        for (int i = tid; i < 64 * 24; i += 256) {
            int r = i / 24, c = (i % 24) * 8;
            *reinterpret_cast<uint4*>(&sBh[r * ASTR + c]) =
                *reinterpret_cast<const uint4*>(&Bh[(size_t)(nt * 64 + r) * 192 + c]);
            *reinterpret_cast<uint4*>(&sBl[r * ASTR + c]) =
                *reinterpret_cast<const uint4*>(&Bl[(size_t)(nt * 64 + r) * 192 + c]);
        }
        __syncthreads();

        float acc[2][4][4];
#pragma unroll
        for (int mt = 0; mt < 2; mt++)
#pragma unroll
            for (int t4 = 0; t4 < 4; t4++)
#pragma unroll
                for (int j = 0; j < 4; j++) acc[mt][t4][j] = 0.f;

#pragma unroll 4
        for (int ks = 0; ks < 12; ks++) {
            const int k0 = ks * 16;
            uint32_t a[2][4], bh[4][2], bl[4][2];
#pragma unroll
            for (int mt = 0; mt < 2; mt++) {
                int row = warpm * 32 + mt * 16 + a_row_off;
                LDSM_X4(a[mt][0], a[mt][1], a[mt][2], a[mt][3],
                        smem_u32(&sA[row * ASTR + k0 + a_col_off]));
            }
#pragma unroll
            for (int pr = 0; pr < 2; pr++) {
                int row = warpn * 32 + pr * 16 + b_row_off;
                LDSM_X4(bh[2 * pr][0], bh[2 * pr][1], bh[2 * pr + 1][0],
                        bh[2 * pr + 1][1],
                        smem_u32(&sBh[row * ASTR + k0 + b_col_off]));
                LDSM_X4(bl[2 * pr][0], bl[2 * pr][1], bl[2 * pr + 1][0],
                        bl[2 * pr + 1][1],
                        smem_u32(&sBl[row * ASTR + k0 + b_col_off]));
            }
#pragma unroll
            for (int mt = 0; mt < 2; mt++)
#pragma unroll
                for (int t4 = 0; t4 < 4; t4++) {
                    MMA_F16(acc[mt][t4], a[mt], bh[t4]);
                    MMA_F16(acc[mt][t4], a[mt], bl[t4]);
                }
        }

        const int qrow = lane >> 2;
        const int qcol = (lane & 3) * 2;
#pragma unroll
        for (int mt = 0; mt < 2; mt++) {
#pragma unroll
            for (int t4 = 0; t4 < 4; t4++) {
                const int col = nt * 64 + warpn * 32 + t4 * 8 + qcol;
                const float b0 = bias[col], b1 = bias[col + 1];
                const int r0 = m_blk + warpm * 32 + mt * 16 + qrow;
                float v00 = acc[mt][t4][0] + b0, v01 = acc[mt][t4][1] + b1;
                float v10 = acc[mt][t4][2] + b0, v11 = acc[mt][t4][3] + b1;
                if (mode == 1) {
                    *reinterpret_cast<float2*>(&out[(size_t)r0 * CDIM + col]) =
                        make_float2(v00, v01);
                    *reinterpret_cast<float2*>(&out[(size_t)(r0 + 8) * CDIM + col]) =
                        make_float2(v10, v11);
                } else {
                    const int t = col / CDIM;
                    const int rem = col - t * CDIM;
                    const int hh = rem >> 5, dd = rem & 31;
                    const int bi0 = r0 / LTOK, l0 = r0 - bi0 * LTOK;
                    const int r1 = r0 + 8;
                    const int bi1 = r1 / LTOK, l1 = r1 - bi1 * LTOK;
                    const size_t o0 = ((size_t)(bi0 * HEADS + hh) * LTOK + l0) * HD + dd;
                    const size_t o1 = ((size_t)(bi1 * HEADS + hh) * LTOK + l1) * HD + dd;
                    if (t == 0) {
                        __half ha, la, hb, lb;
                        hsplit(v00 * QK_SCALE, ha, la); hsplit(v01 * QK_SCALE, hb, lb);
                        *reinterpret_cast<__half2*>(g_Qh + o0) = __halves2half2(ha, hb);
                        *reinterpret_cast<__half2*>(g_Ql + o0) = __halves2half2(la, lb);
                        hsplit(v10 * QK_SCALE, ha, la); hsplit(v11 * QK_SCALE, hb, lb);
                        *reinterpret_cast<__half2*>(g_Qh + o1) = __halves2half2(ha, hb);
                        *reinterpret_cast<__half2*>(g_Ql + o1) = __halves2half2(la, lb);
                    } else if (t == 1) {
                        *reinterpret_cast<__half2*>(g_Kh + o0) =
                            __floats2half2_rn(v00, v01);
                        *reinterpret_cast<__half2*>(g_Kh + o1) =
                            __floats2half2_rn(v10, v11);
                    } else {
                        __half ha, la, hb, lb;
                        hsplit(v00, ha, la); hsplit(v01, hb, lb);
                        *reinterpret_cast<__half2*>(g_Vh + o0) = __halves2half2(ha, hb);
                        *reinterpret_cast<__half2*>(g_Vl + o0) = __halves2half2(la, lb);
                        hsplit(v10, ha, la); hsplit(v11, hb, lb);
                        *reinterpret_cast<__half2*>(g_Vh + o1) = __halves2half2(ha, hb);
                        *reinterpret_cast<__half2*>(g_Vl + o1) = __halves2half2(la, lb);
                    }
                }
            }
        }
        __syncthreads();
    }
}

// ---------------------------------------------------------------------------
// K2: register-resident mma attention. CTA = (window, head), 288 threads,
// 2 CTAs/SM allowed (54KB SMEM).
// ---------------------------------------------------------------------------
#define QSTR 40
#define VTSTR 152
#define ATTN_SMEM (3 * 144 * QSTR * 2 + 2 * 32 * VTSTR * 2)   // 54016 B

__global__ __launch_bounds__(288, 2) void attn_mma_kernel(const float* __restrict__ mask) {
    extern __shared__ __align__(16) char sraw[];
    __half* sQh = reinterpret_cast<__half*>(sraw);
    __half* sQl = sQh + 144 * QSTR;
    __half* sKh = sQl + 144 * QSTR;
    __half* sVh = sKh + 144 * QSTR;          // [32][VTSTR] transposed
    __half* sVl = sVh + 32 * VTSTR;

    const int bh = blockIdx.x;
    const int b = bh / HEADS, h = bh % HEADS;
    const int nw = b / WWINS;
    const int tid = threadIdx.x;
    const int warp = tid >> 5, lane = tid & 31;
    const size_t base = (size_t)bh * (LTOK * HD);

    for (int c = tid; c < 576; c += 288) {
        int l = c >> 2, dp = (c & 3) * 8;
        *reinterpret_cast<uint4*>(&sQh[l * QSTR + dp]) =
            *reinterpret_cast<const uint4*>(&g_Qh[base + l * 32 + dp]);
        *reinterpret_cast<uint4*>(&sQl[l * QSTR + dp]) =
            *reinterpret_cast<const uint4*>(&g_Ql[base + l * 32 + dp]);
        *reinterpret_cast<uint4*>(&sKh[l * QSTR + dp]) =
            *reinterpret_cast<const uint4*>(&g_Kh[base + l * 32 + dp]);
    }
    for (int i = tid; i < 2304; i += 288) {
        int l = i >> 4, d2 = (i & 15) * 2;
        __half2 vh = *reinterpret_cast<const __half2*>(&g_Vh[base + l * 32 + d2]);
        __half2 vl = *reinterpret_cast<const __half2*>(&g_Vl[base + l * 32 + d2]);
        sVh[d2 * VTSTR + l] = __low2half(vh);
        sVh[(d2 + 1) * VTSTR + l] = __high2half(vh);
        sVl[d2 * VTSTR + l] = __low2half(vl);
        sVl[(d2 + 1) * VTSTR + l] = __high2half(vl);
    }
    __syncthreads();

    const int lr = lane & 7, sel = lane >> 3;
    const int arow = lr + (sel & 1) * 8, acol = (sel >> 1) * 8;
    const int brow = lr + (sel >> 1) * 8, bcol = (sel & 1) * 8;
    const int g = lane >> 2, tg = lane & 3;

    uint32_t qh[2][4], ql[2][4];
#pragma unroll
    for (int ks = 0; ks < 2; ks++) {
        LDSM_X4(qh[ks][0], qh[ks][1], qh[ks][2], qh[ks][3],
                smem_u32(&sQh[(warp * 16 + arow) * QSTR + ks * 16 + acol]));
        LDSM_X4(ql[ks][0], ql[ks][1], ql[ks][2], ql[ks][3],
                smem_u32(&sQl[(warp * 16 + arow) * QSTR + ks * 16 + acol]));
    }

    float acc[18][4];
#pragma unroll
    for (int nb = 0; nb < 18; nb++)
#pragma unroll
        for (int j = 0; j < 4; j++) acc[nb][j] = 0.f;

#pragma unroll 3
    for (int nt = 0; nt < 9; nt++) {
#pragma unroll
        for (int ks = 0; ks < 2; ks++) {
            uint32_t kh[4];
            LDSM_X4(kh[0], kh[1], kh[2], kh[3],
                    smem_u32(&sKh[(nt * 16 + brow) * QSTR + ks * 16 + bcol]));
            MMA_F16(acc[2 * nt],     qh[ks], kh + 0);
            MMA_F16(acc[2 * nt + 1], qh[ks], kh + 2);
            MMA_F16(acc[2 * nt],     ql[ks], kh + 0);
            MMA_F16(acc[2 * nt + 1], ql[ks], kh + 2);
        }
    }

    const float* biasrow = g_bias + (size_t)(nw * HEADS + h) * (LTOK * LTOK);
    const float* maskrow = mask + (size_t)b * (LTOK * LTOK);
    const int r0 = warp * 16 + g;
    const int r1 = r0 + 8;
#pragma unroll
    for (int nb = 0; nb < 18; nb++) {
        const int cc = nb * 8 + tg * 2;
        float2 b0 = *reinterpret_cast<const float2*>(&biasrow[r0 * LTOK + cc]);
        float2 m0 = *reinterpret_cast<const float2*>(&maskrow[r0 * LTOK + cc]);
        float2 b1 = *reinterpret_cast<const float2*>(&biasrow[r1 * LTOK + cc]);
        float2 m1 = *reinterpret_cast<const float2*>(&maskrow[r1 * LTOK + cc]);
        acc[nb][0] += b0.x + m0.x;
        acc[nb][1] += b0.y + m0.y;
        acc[nb][2] += b1.x + m1.x;
        acc[nb][3] += b1.y + m1.y;
    }
    float mx0 = -1e30f, mx1 = -1e30f;
#pragma unroll
    for (int nb = 0; nb < 18; nb++) {
        mx0 = fmaxf(mx0, fmaxf(acc[nb][0], acc[nb][1]));
        mx1 = fmaxf(mx1, fmaxf(acc[nb][2], acc[nb][3]));
    }
    mx0 = fmaxf(mx0, __shfl_xor_sync(0xffffffffu, mx0, 1));
    mx0 = fmaxf(mx0, __shfl_xor_sync(0xffffffffu, mx0, 2));
    mx1 = fmaxf(mx1, __shfl_xor_sync(0xffffffffu, mx1, 1));
    mx1 = fmaxf(mx1, __shfl_xor_sync(0xffffffffu, mx1, 2));
    float s0 = 0.f, s1 = 0.f;
#pragma unroll
    for (int nb = 0; nb < 18; nb++) {
        acc[nb][0] = __expf(acc[nb][0] - mx0);
        acc[nb][1] = __expf(acc[nb][1] - mx0);
        acc[nb][2] = __expf(acc[nb][2] - mx1);
        acc[nb][3] = __expf(acc[nb][3] - mx1);
        s0 += acc[nb][0] + acc[nb][1];
        s1 += acc[nb][2] + acc[nb][3];
    }
    s0 += __shfl_xor_sync(0xffffffffu, s0, 1);
    s0 += __shfl_xor_sync(0xffffffffu, s0, 2);
    s1 += __shfl_xor_sync(0xffffffffu, s1, 1);
    s1 += __shfl_xor_sync(0xffffffffu, s1, 2);
    const float inv0 = 1.f / s0, inv1 = 1.f / s1;

    float o[4][4];
#pragma unroll
    for (int nb = 0; nb < 4; nb++)
#pragma unroll
        for (int j = 0; j < 4; j++) o[nb][j] = 0.f;

#pragma unroll 3
    for (int ks = 0; ks < 9; ks++) {
        uint32_t a[4];
        a[0] = pack_h2(acc[2 * ks][0] * inv0, acc[2 * ks][1] * inv0);
        a[1] = pack_h2(acc[2 * ks][2] * inv1, acc[2 * ks][3] * inv1);
        a[2] = pack_h2(acc[2 * ks + 1][0] * inv0, acc[2 * ks + 1][1] * inv0);
        a[3] = pack_h2(acc[2 * ks + 1][2] * inv1, acc[2 * ks + 1][3] * inv1);
#pragma unroll
        for (int ntv = 0; ntv < 2; ntv++) {
            uint32_t vh[4], vl[4];
            LDSM_X4(vh[0], vh[1], vh[2], vh[3],
                    smem_u32(&sVh[(ntv * 16 + brow) * VTSTR + ks * 16 + bcol]));
            LDSM_X4(vl[0], vl[1], vl[2], vl[3],
                    smem_u32(&sVl[(ntv * 16 + brow) * VTSTR + ks * 16 + bcol]));
            MMA_F16(o[2 * ntv],     a, vh + 0);
            MMA_F16(o[2 * ntv + 1], a, vh + 2);
            MMA_F16(o[2 * ntv],     a, vl + 0);
            MMA_F16(o[2 * ntv + 1], a, vl + 2);
        }
    }

#pragma unroll
    for (int nb = 0; nb < 4; nb++) {
        const int d0 = nb * 8 + tg * 2;
        const size_t off0 = ((size_t)b * LTOK + r0) * CDIM + h * HD + d0;
        const size_t off1 = ((size_t)b * LTOK + r1) * CDIM + h * HD + d0;
        *reinterpret_cast<float2*>(&g_ctx[off0]) = make_float2(o[nb][0], o[nb][1]);
        *reinterpret_cast<float2*>(&g_ctx[off1]) = make_float2(o[nb][2], o[nb][3]);
    }
}

// ---------------------------------------------------------------------------
extern "C" void kernel_launch(void* const* d_in, const int* in_sizes, int n_in,
                              void* d_out, int out_size) {
    const float* x    = (const float*)d_in[0];
    const float* mask = (const float*)d_in[1];
    const float* W1   = (const float*)d_in[2];
    const float* b1   = (const float*)d_in[3];
    const float* W2   = (const float*)d_in[4];
    const float* b2   = (const float*)d_in[5];
    const float* btab = (const float*)d_in[6];
    const int*   pidx = (const int*)d_in[7];
    float* out = (float*)d_out;
    (void)in_sizes; (void)n_in; (void)out_size;

    cudaFuncSetAttribute(mma_gemm_kernel,
                         cudaFuncAttributeMaxDynamicSharedMemorySize, GEMM_SMEM);
    cudaFuncSetAttribute(attn_mma_kernel,
                         cudaFuncAttributeMaxDynamicSharedMemorySize, ATTN_SMEM);

    __half *w1h, *w1l, *w2h, *w2l;
    float* ctx;
    cudaGetSymbolAddress((void**)&w1h, g_W1h);
    cudaGetSymbolAddress((void**)&w1l, g_W1l);
    cudaGetSymbolAddress((void**)&w2h, g_W2h);
    cudaGetSymbolAddress((void**)&w2l, g_W2l);
    cudaGetSymbolAddress((void**)&ctx, g_ctx);

    splitW_kernel<<<(576 * 192 + 255) / 256, 256>>>(W1, w1h, w1l, 576);
    splitW_kernel<<<(192 * 192 + 255) / 256, 256>>>(W2, w2h, w2l, 192);
    bias_gather_kernel<<<NW * HEADS * 4, 256>>>(btab, pidx);

    mma_gemm_kernel<<<MTOT / 128, 256, GEMM_SMEM>>>(x, w1h, w1l, b1, 9, 0, nullptr);
    attn_mma_kernel<<<NWIN * HEADS, 288, ATTN_SMEM>>>(mask);
    mma_gemm_kernel<<<MTOT / 128, 256, GEMM_SMEM>>>(ctx, w2h, w2l, b2, 3, 1, out);
}